// round 5
// baseline (speedup 1.0000x reference)
#include <cuda_runtime.h>

#define BN 8
#define JN 64
#define CN 32
#define CG 8               // channels per block (grid.z = CN/CG = 4)
#define HT 8
#define HIMG_ 256
#define WIMG_ 256
#define HW (HIMG_*WIMG_)

// mask_mode: 0 = float mask after res, 1 = uint8 mask packed after res, 2 = no mask
__global__ void __launch_bounds__(256, 6)
roirotate_kernel(const float* __restrict__ image,
                 const float* __restrict__ boxes,
                 float* __restrict__ out,
                 int max_w, int mask_mode)
{
    const int bj = blockIdx.y;               // 0 .. B*J-1
    const int b  = bj >> 6;                  // JN = 64
    const int c0 = blockIdx.z * CG;

    const float* bx = boxes + bj * 5;
    float l   = bx[0];
    float t   = bx[1];
    float r   = bx[2];
    float btm = bx[3];

    float bw = __fsub_rn(r, l);
    float bh = __fsub_rn(btm, t);
    // widths = int32( (bw/bh) * 8 )  in float32 arithmetic, truncation toward zero
    int width = (int)(__fmul_rn(__fdiv_rn(bw, bh), 8.0f));
    float each_w = __fdiv_rn(bw, (float)(width - 1));
    float each_h = __fdiv_rn(bh, 7.0f);   // HEIGHT-1 = 7

    const int chw = HT * max_w;              // per-channel output stride (elements)
    const float* imgb = image + (b * CN + c0) * HW;
    float* outb = out + (bj * CN + c0) * chw;

    const int idx = blockIdx.x * blockDim.x + threadIdx.x;   // over HT*max_w

    // ---- mask (only one slice of blocks writes it) ----
    if (blockIdx.x == 0 && blockIdx.z == 0) {
        if (mask_mode == 0) {
            float* maskp = out + BN * JN * CN * chw + bj * max_w;
            for (int k = threadIdx.x; k < max_w; k += blockDim.x)
                maskp[k] = (k < width) ? 1.0f : 0.0f;
        } else if (mask_mode == 1) {
            unsigned char* maskp =
                (unsigned char*)(out + BN * JN * CN * chw) + bj * max_w;
            for (int k = threadIdx.x; k < max_w; k += blockDim.x)
                maskp[k] = (k < width) ? (unsigned char)1 : (unsigned char)0;
        }
    }

    if (idx >= chw) return;

    const int k = idx % max_w;
    const int i = idx / max_w;
    float* op = outb + idx;                   // == outb + i*max_w + k

    if (k >= width) {
        // masked region -> zeros (output buffer is poisoned, must write)
        float* o = op;
        #pragma unroll
        for (int c = 0; c < CG; c++) { *o = 0.0f; o += chw; }
        return;
    }

    // coordinate generation: match JAX float32 mul-then-add exactly (no FMA)
    float x = __fadd_rn(__fmul_rn((float)k, each_w), l);
    float y = __fadd_rn(__fmul_rn((float)i, each_h), t);

    float fx = floorf(x), fy = floorf(y);
    int x0 = min(max((int)fx,     0), WIMG_ - 1);
    int x1 = min(max((int)fx + 1, 0), WIMG_ - 1);
    int y0 = min(max((int)fy,     0), HIMG_ - 1);
    int y1 = min(max((int)fy + 1, 0), HIMG_ - 1);

    float x0f = (float)x0, x1f = (float)x1;
    float y0f = (float)y0, y1f = (float)y1;
    float wa = (x1f - x) * (y1f - y);   // (y0,x0)
    float wb = (x1f - x) * (y - y0f);   // (y1,x0)
    float wc = (x - x0f) * (y1f - y);   // (y0,x1)
    float wd = (x - x0f) * (y - y0f);   // (y1,x1)

    const int o00 = y0 * WIMG_ + x0;
    const int o10 = y1 * WIMG_ + x0;
    const int o01 = y0 * WIMG_ + x1;
    const int o11 = y1 * WIMG_ + x1;

    // CG/4 = 2 groups of 4 channels: 16 independent LDGs batched per group
    // (per-warp outstanding-LDG cap ~55, so 16/thread is ample),
    // then 4 FMA chains + 4 coalesced stores.
    const float* ip = imgb;
    float* o = op;
    #pragma unroll
    for (int g = 0; g < CG / 4; g++) {
        float a0 = __ldg(ip + o00), b0 = __ldg(ip + o10), c0v = __ldg(ip + o01), d0 = __ldg(ip + o11);
        float a1 = __ldg(ip + HW + o00), b1 = __ldg(ip + HW + o10), c1v = __ldg(ip + HW + o01), d1 = __ldg(ip + HW + o11);
        float a2 = __ldg(ip + 2*HW + o00), b2 = __ldg(ip + 2*HW + o10), c2v = __ldg(ip + 2*HW + o01), d2 = __ldg(ip + 2*HW + o11);
        float a3 = __ldg(ip + 3*HW + o00), b3 = __ldg(ip + 3*HW + o10), c3v = __ldg(ip + 3*HW + o01), d3 = __ldg(ip + 3*HW + o11);

        o[0]       = a0 * wa + b0 * wb + c0v * wc + d0 * wd;
        o[chw]     = a1 * wa + b1 * wb + c1v * wc + d1 * wd;
        o[2 * chw] = a2 * wa + b2 * wb + c2v * wc + d2 * wd;
        o[3 * chw] = a3 * wa + b3 * wb + c3v * wc + d3 * wd;

        ip += 4 * HW;
        o  += 4 * chw;
    }
}

extern "C" void kernel_launch(void* const* d_in, const int* in_sizes, int n_in,
                              void* d_out, int out_size)
{
    const float* image = (const float*)d_in[0];
    const float* boxes = (const float*)d_in[1];
    float* out = (float*)d_out;

    // Derive max_w from out_size (host-side, no sync needed).
    // res elems per unit max_w: B*J*C*H = 131072 ; mask elems per unit: B*J = 512
    const long long per_res = (long long)BN * JN * CN * HT;     // 131072
    const long long per_fmask = per_res + (long long)BN * JN;   // 131584 (float mask)
    const long long per_u8 = per_res + (long long)BN * JN / 4;  // 131200 (u8 mask packed into f32 elems)

    int max_w, mask_mode;
    long long osz = (long long)out_size;
    if (osz % per_fmask == 0) {
        max_w = (int)(osz / per_fmask);
        mask_mode = 0;
    } else if (osz % per_u8 == 0) {
        max_w = (int)(osz / per_u8);
        mask_mode = 1;
    } else if (osz % per_res == 0) {
        max_w = (int)(osz / per_res);
        mask_mode = 2;
    } else {
        // fallback: assume float-mask layout, round down
        max_w = (int)(osz / per_fmask);
        mask_mode = 0;
    }

    const int block = 256;
    int slices = (HT * max_w + block - 1) / block;
    dim3 grid(slices, BN * JN, CN / CG);
    roirotate_kernel<<<grid, block>>>(image, boxes, out, max_w, mask_mode);
}